// round 2
// baseline (speedup 1.0000x reference)
#include <cuda_runtime.h>

#define DD 64
#define HH 32
#define MAXS 16384
#define TPB 256
#define RPT 8   // rows per thread (4 iterations x 2 rows)

// scratch accumulators (no cudaMalloc allowed)
__device__ float g_denom[MAXS];
__device__ float g_numer[MAXS];

__device__ __forceinline__ unsigned long long ffma2(unsigned long long a,
                                                    unsigned long long b,
                                                    unsigned long long c) {
    unsigned long long d;
    asm("fma.rn.f32x2 %0, %1, %2, %3;" : "=l"(d) : "l"(a), "l"(b), "l"(c));
    return d;
}

__device__ __forceinline__ unsigned long long pack2(float lo, float hi) {
    unsigned long long d;
    asm("mov.b64 %0, {%1, %2};" : "=l"(d) : "f"(lo), "f"(hi));
    return d;
}

__device__ __forceinline__ float2 unpack2(unsigned long long v) {
    float2 f;
    asm("mov.b64 {%0, %1}, %2;" : "=f"(f.x), "=f"(f.y) : "l"(v));
    return f;
}

__global__ void zero_kernel(int S) {
    int i = blockIdx.x * blockDim.x + threadIdx.x;
    if (i < S) { g_denom[i] = 0.0f; g_numer[i] = 0.0f; }
}

__device__ __forceinline__ void finish_row(
    const unsigned long long* h, long long row, bool valid,
    const unsigned long long* swr, const unsigned long long* swz,
    float brv, float bzv, const int* __restrict__ seg)
{
    float r = brv, z = bzv;
#pragma unroll
    for (int j = 0; j < 16; j++) {
        float2 hp  = unpack2(h[j]);
        float2 wrp = unpack2(swr[j]);
        float2 wzp = unpack2(swz[j]);
        float h0 = fmaxf(hp.x, 0.0f);
        float h1 = fmaxf(hp.y, 0.0f);
        r = fmaf(h0, wrp.x, r); r = fmaf(h1, wrp.y, r);
        z = fmaf(h0, wzp.x, z); z = fmaf(h1, wzp.y, z);
    }
    // softmax shift cancels exactly in numer/denom; z is O(1) here so exp(z) is safe.
    float ez = valid ? __expf(z) : 0.0f;
    float nz = ez * r;
    int   s  = valid ? seg[row] : -1;

    // segment_ids are sorted and a warp covers 32 consecutive rows -> most
    // warps are segment-uniform. Aggregate in-warp, then one REDG per warp.
    int s0 = __shfl_sync(0xFFFFFFFFu, s, 0);
    bool uniform = __all_sync(0xFFFFFFFFu, s == s0);
    if (uniform) {
        if (s0 < 0) return;   // whole warp invalid
#pragma unroll
        for (int off = 16; off > 0; off >>= 1) {
            ez += __shfl_xor_sync(0xFFFFFFFFu, ez, off);
            nz += __shfl_xor_sync(0xFFFFFFFFu, nz, off);
        }
        if ((threadIdx.x & 31) == 0) {
            atomicAdd(&g_denom[s0], ez);
            atomicAdd(&g_numer[s0], nz);
        }
    } else if (s >= 0) {
        atomicAdd(&g_denom[s], ez);
        atomicAdd(&g_numer[s], nz);
    }
}

__global__ __launch_bounds__(TPB)
void poc_main_kernel(const float* __restrict__ x,
                     const float* __restrict__ W1,
                     const float* __restrict__ b1,
                     const float* __restrict__ wr,
                     const float* __restrict__ br,
                     const float* __restrict__ wz,
                     const float* __restrict__ bz,
                     const int*   __restrict__ seg,
                     int N)
{
    // W1 [64,32] row-major: adjacent h-pairs contiguous -> read as packed u64 pairs.
    __shared__ unsigned long long sW[DD * 16];   // 8 KB
    __shared__ unsigned long long sb1[16], swr[16], swz[16];
    __shared__ float sbr, sbz;

    const unsigned long long* W1p = (const unsigned long long*)W1;
    for (int i = threadIdx.x; i < DD * 16; i += blockDim.x) sW[i] = W1p[i];
    if (threadIdx.x < 16) {
        sb1[threadIdx.x] = ((const unsigned long long*)b1)[threadIdx.x];
        swr[threadIdx.x] = ((const unsigned long long*)wr)[threadIdx.x];
        swz[threadIdx.x] = ((const unsigned long long*)wz)[threadIdx.x];
    }
    if (threadIdx.x == 0) { sbr = *br; sbz = *bz; }
    __syncthreads();

    const long long G   = (long long)gridDim.x * blockDim.x;
    const long long gid = (long long)blockIdx.x * blockDim.x + threadIdx.x;
    const float brv = sbr, bzv = sbz;

#pragma unroll 1
    for (int m = 0; m < RPT / 2; m++) {
        long long rowA = gid + (long long)(2 * m) * G;
        long long rowB = rowA + G;
        bool vA = rowA < N;
        bool vB = rowB < N;
        const float4* xA = (const float4*)(x + (vA ? rowA : 0) * DD);
        const float4* xB = (const float4*)(x + (vB ? rowB : 0) * DD);

        unsigned long long hA[16], hB[16];
#pragma unroll
        for (int j = 0; j < 16; j++) { hA[j] = sb1[j]; hB[j] = sb1[j]; }

#pragma unroll 1
        for (int k4 = 0; k4 < 16; k4++) {
            float4 a  = xA[k4];
            float4 bv = xB[k4];
            float aa[4] = {a.x, a.y, a.z, a.w};
            float bb[4] = {bv.x, bv.y, bv.z, bv.w};
#pragma unroll
            for (int kk = 0; kk < 4; kk++) {
                int k = 4 * k4 + kk;
                unsigned long long a2 = pack2(aa[kk], aa[kk]);
                unsigned long long b2 = pack2(bb[kk], bb[kk]);
#pragma unroll
                for (int q = 0; q < 8; q++) {
                    ulonglong2 w = *(const ulonglong2*)&sW[k * 16 + 2 * q];
                    hA[2 * q]     = ffma2(w.x, a2, hA[2 * q]);
                    hA[2 * q + 1] = ffma2(w.y, a2, hA[2 * q + 1]);
                    hB[2 * q]     = ffma2(w.x, b2, hB[2 * q]);
                    hB[2 * q + 1] = ffma2(w.y, b2, hB[2 * q + 1]);
                }
            }
        }
        finish_row(hA, rowA, vA, swr, swz, brv, bzv, seg);
        finish_row(hB, rowB, vB, swr, swz, brv, bzv, seg);
    }
}

__global__ void finalize_kernel(float* __restrict__ out, int S) {
    const float SCALEC   = 173.7177927613007f;   // 400/ln(10)
    const float DEFAULTC = 7.6699353278706015f;
    int s = blockIdx.x * blockDim.x + threadIdx.x;
    if (s < S) {
        float d = g_denom[s];
        float pred = (d > 0.0f) ? (g_numer[s] / d) : DEFAULTC;
        out[s] = SCALEC * pred;
    }
}

extern "C" void kernel_launch(void* const* d_in, const int* in_sizes, int n_in,
                              void* d_out, int out_size) {
    const float* x   = (const float*)d_in[0];
    const float* W1  = (const float*)d_in[1];
    const float* b1  = (const float*)d_in[2];
    const float* wr  = (const float*)d_in[3];
    const float* br  = (const float*)d_in[4];
    const float* wz  = (const float*)d_in[5];
    const float* bz  = (const float*)d_in[6];
    const int*   seg = (const int*)d_in[7];

    int N = in_sizes[0] / DD;
    int S = out_size;
    if (S > MAXS) S = MAXS;
    float* out = (float*)d_out;

    zero_kernel<<<(S + TPB - 1) / TPB, TPB>>>(S);

    long long threads = ((long long)N + RPT - 1) / RPT;
    int blocks = (int)((threads + TPB - 1) / TPB);
    poc_main_kernel<<<blocks, TPB>>>(x, W1, b1, wr, br, wz, bz, seg, N);

    finalize_kernel<<<(S + TPB - 1) / TPB, TPB>>>(out, S);
}

// round 9
// speedup vs baseline: 2.5038x; 2.5038x over previous
#include <cuda_runtime.h>
#include <cuda_bf16.h>
#include <cstdint>

#define MAXS      16384
#define TPB       128
#define TILE_ROWS 64
#define DD        64
#define HH        32
#define GRID_MAIN 592   // 4 CTAs/SM x 148 SMs (persistent)

// scratch accumulators (no cudaMalloc allowed)
__device__ float g_denom[MAXS];
__device__ float g_numer[MAXS];

__device__ __forceinline__ uint32_t smem_u32(const void* p) {
    uint32_t a;
    asm("{ .reg .u64 t; cvta.to.shared.u64 t, %1; cvt.u32.u64 %0, t; }"
        : "=r"(a) : "l"(p));
    return a;
}

__device__ __forceinline__ void ldsm4(uint32_t r[4], uint32_t addr) {
    asm volatile("ldmatrix.sync.aligned.m8n8.x4.shared.b16 {%0,%1,%2,%3}, [%4];"
        : "=r"(r[0]), "=r"(r[1]), "=r"(r[2]), "=r"(r[3]) : "r"(addr));
}

__device__ __forceinline__ void mma_bf16(float d[4], const uint32_t a[4], const uint32_t b[2]) {
    asm volatile(
        "mma.sync.aligned.m16n8k16.row.col.f32.bf16.bf16.f32 "
        "{%0,%1,%2,%3}, {%4,%5,%6,%7}, {%8,%9}, {%0,%1,%2,%3};"
        : "+f"(d[0]), "+f"(d[1]), "+f"(d[2]), "+f"(d[3])
        : "r"(a[0]), "r"(a[1]), "r"(a[2]), "r"(a[3]), "r"(b[0]), "r"(b[1]));
}

__device__ __forceinline__ uint32_t pack_bf16x2(float lo, float hi) {
    __nv_bfloat162 p = __floats2bfloat162_rn(lo, hi);   // .x = lo (low 16 bits)
    return *reinterpret_cast<uint32_t*>(&p);
}

__global__ void zero_kernel(int S) {
    int i = blockIdx.x * blockDim.x + threadIdx.x;
    if (i < S) { g_denom[i] = 0.0f; g_numer[i] = 0.0f; }
}

__global__ __launch_bounds__(TPB, 4)
void poc_mma_kernel(const float* __restrict__ x,
                    const float* __restrict__ W1,
                    const float* __restrict__ b1,
                    const float* __restrict__ wr,
                    const float* __restrict__ br,
                    const float* __restrict__ wz,
                    const float* __restrict__ bz,
                    const int*   __restrict__ seg,
                    int N)
{
    // A tile as bf16 (hi + residual lo), 64 rows x 64 cols, row stride 128B,
    // 16B-chunk swizzle (ch ^ (row&7)) -> conflict-free STS.128 and ldmatrix.
    __shared__ __align__(128) __nv_bfloat16 smHi[TILE_ROWS * DD];   // 8 KB
    __shared__ __align__(128) __nv_bfloat16 smLo[TILE_ROWS * DD];   // 8 KB
    __shared__ __align__(16)  float smCol[HH * 4];                  // {b1, wr, wz, 0} per col

    const int tid  = threadIdx.x;
    const int wid  = tid >> 5;
    const int lane = tid & 31;

    if (tid < HH) {
        smCol[4 * tid + 0] = b1[tid];
        smCol[4 * tid + 1] = wr[tid];
        smCol[4 * tid + 2] = wz[tid];
        smCol[4 * tid + 3] = 0.0f;
    }

    // ---- B fragments: W1^T split hi + residual lo, bf16, in registers ----
    // m16n8k16 B frag (col-major B): b0 = {B[k0][n], B[k0+1][n]},
    // b1 = {B[k0+8][n], B[k0+9][n]}, k0 = (lane&3)*2, n = lane>>2.
    // 3-pass compensated product: Ah*Bh + Al*Bh + Ah*Bl  (Al*Bl ~ 2^-18, dropped)
    uint32_t Bh[4][4][2], Bl[4][4][2];
    {
        const int kq = (lane & 3) * 2;
        const int n  = lane >> 2;
#pragma unroll
        for (int kc = 0; kc < 4; kc++)
#pragma unroll
            for (int nt = 0; nt < 4; nt++) {
                int k0  = kc * 16 + kq;
                int col = nt * 8 + n;
                float w00 = W1[k0 * HH + col],       w01 = W1[(k0 + 1) * HH + col];
                float w10 = W1[(k0 + 8) * HH + col], w11 = W1[(k0 + 9) * HH + col];
                __nv_bfloat162 h0 = __floats2bfloat162_rn(w00, w01);
                __nv_bfloat162 h1 = __floats2bfloat162_rn(w10, w11);
                Bh[kc][nt][0] = *reinterpret_cast<uint32_t*>(&h0);
                Bh[kc][nt][1] = *reinterpret_cast<uint32_t*>(&h1);
                Bl[kc][nt][0] = pack_bf16x2(w00 - __bfloat162float(h0.x),
                                            w01 - __bfloat162float(h0.y));
                Bl[kc][nt][1] = pack_bf16x2(w10 - __bfloat162float(h1.x),
                                            w11 - __bfloat162float(h1.y));
            }
    }
    __syncthreads();

    const float brv = *br, bzv = *bz;
    const float4* __restrict__ x4 = (const float4*)x;
    const int TILES = (N + TILE_ROWS - 1) / TILE_ROWS;
    const uint32_t hiBase = smem_u32(smHi);
    const uint32_t loBase = smem_u32(smLo);

    for (int t = blockIdx.x; t < TILES; t += gridDim.x) {
        const long long rowBase = (long long)t * TILE_ROWS;

        // ---- stage: fp32 gmem -> (hi, lo) bf16 smem; coalesced 32B/thread ----
#pragma unroll
        for (int i = 0; i < 4; i++) {
            int g   = i * TPB + tid;      // 0..511
            int row = g >> 3;             // 0..63
            int ch  = g & 7;              // 16B-bf16 chunk (= 8 fp32)
            float4 v0 = make_float4(0.f, 0.f, 0.f, 0.f), v1 = v0;
            if (rowBase + row < N) {
                size_t f4i = (size_t)(rowBase + row) * 16 + ch * 2;
                v0 = x4[f4i];
                v1 = x4[f4i + 1];
            }
            float f[8] = {v0.x, v0.y, v0.z, v0.w, v1.x, v1.y, v1.z, v1.w};
            uint32_t hu[4], lu[4];
#pragma unroll
            for (int j = 0; j < 4; j++) {
                __nv_bfloat162 h = __floats2bfloat162_rn(f[2 * j], f[2 * j + 1]);
                hu[j] = *reinterpret_cast<uint32_t*>(&h);
                float l0 = f[2 * j]     - __bfloat162float(h.x);
                float l1 = f[2 * j + 1] - __bfloat162float(h.y);
                lu[j] = pack_bf16x2(l0, l1);
            }
            uint32_t off = (uint32_t)row * 128 + (uint32_t)((ch ^ (row & 7)) << 4);
            *(uint4*)((char*)smHi + off) = make_uint4(hu[0], hu[1], hu[2], hu[3]);
            *(uint4*)((char*)smLo + off) = make_uint4(lu[0], lu[1], lu[2], lu[3]);
        }
        __syncthreads();

        // ---- compute: each warp owns 16 rows; 3 compensated MMA passes ----
        const int wrow = wid * 16;
        float D[4][4];
#pragma unroll
        for (int nt = 0; nt < 4; nt++)
#pragma unroll
            for (int j = 0; j < 4; j++) D[nt][j] = 0.0f;

        const int lrow   = wrow + (lane & 7) + ((lane >> 3) & 1) * 8;
        const int chalf  = (lane >> 4) & 1;
#pragma unroll
        for (int kc = 0; kc < 4; kc++) {
            int ch = kc * 2 + chalf;
            uint32_t off = (uint32_t)lrow * 128 + (uint32_t)((ch ^ (lrow & 7)) << 4);
            uint32_t Ah[4], Al[4];
            ldsm4(Ah, hiBase + off);
            ldsm4(Al, loBase + off);
#pragma unroll
            for (int nt = 0; nt < 4; nt++) {
                mma_bf16(D[nt], Ah, Bh[kc][nt]);
                mma_bf16(D[nt], Al, Bh[kc][nt]);
                mma_bf16(D[nt], Ah, Bl[kc][nt]);
            }
        }

        // ---- epilogue: relu + r/z dots (fp32), quad reduce, segment atomics ----
        float ra0 = 0.f, za0 = 0.f, ra1 = 0.f, za1 = 0.f;
#pragma unroll
        for (int nt = 0; nt < 4; nt++) {
            int c0 = nt * 8 + (lane & 3) * 2;
            float4 cA = *(const float4*)&smCol[4 * c0];        // {b1,wr,wz,0} col c0
            float4 cB = *(const float4*)&smCol[4 * (c0 + 1)];  // col c0+1
            float h00 = fmaxf(D[nt][0] + cA.x, 0.f);
            float h01 = fmaxf(D[nt][1] + cB.x, 0.f);
            float h10 = fmaxf(D[nt][2] + cA.x, 0.f);
            float h11 = fmaxf(D[nt][3] + cB.x, 0.f);
            ra0 = fmaf(h00, cA.y, ra0); ra0 = fmaf(h01, cB.y, ra0);
            za0 = fmaf(h00, cA.z, za0); za0 = fmaf(h01, cB.z, za0);
            ra1 = fmaf(h10, cA.y, ra1); ra1 = fmaf(h11, cB.y, ra1);
            za1 = fmaf(h10, cA.z, za1); za1 = fmaf(h11, cB.z, za1);
        }
#pragma unroll
        for (int off = 1; off <= 2; off <<= 1) {   // complete 32-col dot within quad
            ra0 += __shfl_xor_sync(0xFFFFFFFFu, ra0, off);
            za0 += __shfl_xor_sync(0xFFFFFFFFu, za0, off);
            ra1 += __shfl_xor_sync(0xFFFFFFFFu, ra1, off);
            za1 += __shfl_xor_sync(0xFFFFFFFFu, za1, off);
        }
        float r0 = ra0 + brv, z0 = za0 + bzv;
        float r1 = ra1 + brv, z1 = za1 + bzv;
        // softmax shift cancels exactly in numer/denom; z is O(1) so exp is safe.
        float ez0 = __expf(z0), nz0 = ez0 * r0;
        float ez1 = __expf(z1), nz1 = ez1 * r1;

        long long gr0 = rowBase + wrow + (lane >> 2);
        long long gr1 = gr0 + 8;
        int s0 = (gr0 < N) ? seg[gr0] : -1;
        int s1 = (gr1 < N) ? seg[gr1] : -1;
        if (s0 < 0) { ez0 = 0.f; nz0 = 0.f; }
        if (s1 < 0) { ez1 = 0.f; nz1 = 0.f; }

        // sorted segment_ids; warp covers 16 consecutive rows -> mostly uniform
        int sref = __shfl_sync(0xFFFFFFFFu, s0, 0);
        bool uni = __all_sync(0xFFFFFFFFu, (s0 == sref) && (s1 == sref));
        if (uni) {
            if (sref >= 0) {
                float e = ez0 + ez1, nm = nz0 + nz1;   // identical within quad
#pragma unroll
                for (int off = 4; off <= 16; off <<= 1) {   // sum the 8 quads
                    e  += __shfl_xor_sync(0xFFFFFFFFu, e, off);
                    nm += __shfl_xor_sync(0xFFFFFFFFu, nm, off);
                }
                if (lane == 0) {
                    atomicAdd(&g_denom[sref], e);
                    atomicAdd(&g_numer[sref], nm);
                }
            }
        } else if ((lane & 3) == 0) {
            if (s0 >= 0) { atomicAdd(&g_denom[s0], ez0); atomicAdd(&g_numer[s0], nz0); }
            if (s1 >= 0) { atomicAdd(&g_denom[s1], ez1); atomicAdd(&g_numer[s1], nz1); }
        }
        __syncthreads();   // smem A fully consumed before next tile's staging
    }
}

__global__ void finalize_kernel(float* __restrict__ out, int S) {
    const float SCALEC   = 173.7177927613007f;   // 400/ln(10)
    const float DEFAULTC = 7.6699353278706015f;
    int s = blockIdx.x * blockDim.x + threadIdx.x;
    if (s < S) {
        float d = g_denom[s];
        float pred = (d > 0.0f) ? (g_numer[s] / d) : DEFAULTC;
        out[s] = SCALEC * pred;
    }
}

extern "C" void kernel_launch(void* const* d_in, const int* in_sizes, int n_in,
                              void* d_out, int out_size) {
    const float* x   = (const float*)d_in[0];
    const float* W1  = (const float*)d_in[1];
    const float* b1  = (const float*)d_in[2];
    const float* wr  = (const float*)d_in[3];
    const float* br  = (const float*)d_in[4];
    const float* wz  = (const float*)d_in[5];
    const float* bz  = (const float*)d_in[6];
    const int*   seg = (const int*)d_in[7];

    int N = in_sizes[0] / DD;
    int S = out_size;
    if (S > MAXS) S = MAXS;
    float* out = (float*)d_out;

    zero_kernel<<<(S + 255) / 256, 256>>>(S);

    int tiles = (N + TILE_ROWS - 1) / TILE_ROWS;
    int grid  = GRID_MAIN < tiles ? GRID_MAIN : tiles;
    poc_mma_kernel<<<grid, TPB>>>(x, W1, b1, wr, br, wz, bz, seg, N);

    finalize_kernel<<<(S + 255) / 256, 256>>>(out, S);
}